// round 1
// baseline (speedup 1.0000x reference)
#include <cuda_runtime.h>
#include <cstdint>
#include <utility>

// ============================================================================
// Compile-time structure builder: replicates the reference _build_structure()
// enumeration exactly (to recover each term's original index for CG_vals),
// then re-sorts terms grouped by (l2, l1, M1, M2) so that consecutive terms
// share the x1[M1]*x2[M2] pair product.
// ============================================================================
namespace wtp {

constexpr int LMAX = 3;
constexpr int MOUT = 16;      // (L+1)^2
constexpr int NNZ  = 478;
constexpr int C    = 128;
constexpr int NCHP = 16;      // channel-pairs per block (32 channels)
constexpr int NROW = 8;       // row slots per block
constexpr int NTHREADS = NCHP * NROW;  // 128

struct Structure {
    int m1[NNZ];
    int m2[NNZ];
    int seg[NNZ];
    int orig[NNZ];     // original reference-order index (for CG table slot)
    bool newpair[NNZ]; // true when (m1,m2) differs from previous term
    int count;
};

constexpr Structure build_structure() {
    Structure s{};
    // --- triples (l, l1, l2), reference enumeration order ---
    int tl[64] = {}, tl1[64] = {}, tl2[64] = {};
    int nt = 0;
    for (int l1 = 0; l1 <= LMAX; l1++)
        for (int l2 = 0; l2 <= LMAX; l2++) {
            int lo = (l1 > l2) ? (l1 - l2) : (l2 - l1);
            int hi = (l1 + l2 < LMAX) ? (l1 + l2) : LMAX;
            for (int l = lo; l <= hi; l++) {
                tl[nt] = l; tl1[nt] = l1; tl2[nt] = l2; nt++;
            }
        }
    // --- terms in reference order (sorted by output Mo, then triple, then m1) ---
    int rm1[NNZ] = {}, rm2[NNZ] = {}, rseg[NNZ] = {}, rl1[NNZ] = {}, rl2[NNZ] = {};
    int cnt = 0;
    for (int l = 0; l <= LMAX; l++)
        for (int m = -l; m <= l; m++) {
            int Mo = l * l + l + m;
            for (int t = 0; t < nt; t++) {
                if (tl[t] != l) continue;
                int l1 = tl1[t], l2 = tl2[t];
                int lo = (-l1 > m - l2) ? -l1 : (m - l2);
                int hi = (l1 < m + l2) ? l1 : (m + l2);
                for (int m1 = lo; m1 <= hi; m1++) {
                    int m2 = m - m1;
                    rm1[cnt] = l1 * l1 + l1 + m1;
                    rm2[cnt] = l2 * l2 + l2 + m2;
                    rseg[cnt] = Mo;
                    rl1[cnt] = l1;
                    rl2[cnt] = l2;
                    cnt++;
                }
            }
        }
    s.count = cnt;
    // --- stable sort by (l2, l1, M1, M2) via rank counting ---
    int key[NNZ] = {};
    for (int i = 0; i < cnt; i++)
        key[i] = (((rl2[i] * 4 + rl1[i]) * 16 + rm1[i]) * 16 + rm2[i]);
    for (int i = 0; i < cnt; i++) {
        int rank = 0;
        for (int j = 0; j < cnt; j++)
            if (key[j] < key[i] || (key[j] == key[i] && j < i)) rank++;
        s.m1[rank]   = rm1[i];
        s.m2[rank]   = rm2[i];
        s.seg[rank]  = rseg[i];
        s.orig[rank] = i;
    }
    for (int i = 0; i < cnt; i++)
        s.newpair[i] = (i == 0) || (s.m1[i] != s.m1[i - 1]) || (s.m2[i] != s.m2[i - 1]);
    return s;
}

constexpr Structure S = build_structure();
static_assert(S.count == NNZ, "term count mismatch vs reference structure");

} // namespace wtp

// ============================================================================
// Hot-loop term executor: one template instantiation per term, all indices
// compile-time constants -> x1/x2/acc stay in registers, LDS has immediate
// offset. Math in packed f32x2 (2 channels per thread).
// ============================================================================
template <int T>
__device__ __forceinline__ void do_term(
    const unsigned long long* __restrict__ cgw_tp,  // = cgw_s + cp
    const unsigned long long (&X1)[wtp::MOUT],
    const unsigned long long (&X2)[wtp::MOUT],
    unsigned long long (&ACC)[wtp::MOUT],
    unsigned long long& p)
{
    constexpr int m1 = wtp::S.m1[T];
    constexpr int m2 = wtp::S.m2[T];
    constexpr int sg = wtp::S.seg[T];
    constexpr int og = wtp::S.orig[T];
    if constexpr (wtp::S.newpair[T]) {
        asm("mul.rn.f32x2 %0, %1, %2;" : "=l"(p) : "l"(X1[m1]), "l"(X2[m2]));
    }
    const unsigned long long wv = cgw_tp[og * wtp::NCHP];
    asm("fma.rn.f32x2 %0, %1, %2, %3;" : "=l"(ACC[sg]) : "l"(p), "l"(wv), "l"(ACC[sg]));
}

template <int... Ts>
__device__ __forceinline__ void run_terms(
    std::integer_sequence<int, Ts...>,
    const unsigned long long* __restrict__ cgw_tp,
    const unsigned long long (&X1)[wtp::MOUT],
    const unsigned long long (&X2)[wtp::MOUT],
    unsigned long long (&ACC)[wtp::MOUT],
    unsigned long long& p)
{
    ((do_term<Ts>(cgw_tp, X1, X2, ACC, p)), ...);
}

// ============================================================================
// Main kernel.
// Block = 128 threads = 16 channel-pairs x 8 row-slots; covers 32 channels
// of 8 batch rows. Grid = (B/8 row groups) x (4 channel groups).
// Shared: cgw[478][16] as f32x2 = 61184 B  -> 3 blocks/SM.
// ============================================================================
__global__ void __launch_bounds__(wtp::NTHREADS, 3)
wtp_kernel(const float* __restrict__ x1,
           const float* __restrict__ x2,
           const float* __restrict__ w,
           const float* __restrict__ cg,
           const int*   __restrict__ l_ind,
           float* __restrict__ out)
{
    extern __shared__ unsigned long long cgw_s[];  // [NNZ * NCHP] packed f32x2

    const int tid     = threadIdx.x;
    const int cgroup  = blockIdx.x & 3;                 // which 32-channel group
    const int rowbase = (blockIdx.x >> 2) * wtp::NROW;  // first batch row
    const int cp      = tid & (wtp::NCHP - 1);          // channel-pair in group
    const int rs      = tid >> 4;                       // row slot 0..7
    const int cbase   = cgroup * 32;

    // --- build per-block CG*weight table from runtime inputs ---
    {
        float2* cgw_f = reinterpret_cast<float2*>(cgw_s);
        #pragma unroll 4
        for (int i = tid; i < wtp::NNZ * wtp::NCHP; i += wtp::NTHREADS) {
            const int t = i >> 4;        // term (reference order)
            const int pc = i & 15;       // channel-pair
            const float cgv = __ldg(cg + t);
            const int li = __ldg(l_ind + t);
            const float2 wv =
                *reinterpret_cast<const float2*>(w + li * wtp::C + cbase + pc * 2);
            cgw_f[i] = make_float2(cgv * wv.x, cgv * wv.y);
        }
    }
    __syncthreads();

    const int row = rowbase + rs;
    const size_t base = (size_t)row * wtp::MOUT * wtp::C + cbase + cp * 2;
    const unsigned long long* x1p = reinterpret_cast<const unsigned long long*>(x1 + base);
    const unsigned long long* x2p = reinterpret_cast<const unsigned long long*>(x2 + base);
    unsigned long long*       op  = reinterpret_cast<unsigned long long*>(out + base);

    unsigned long long X1[wtp::MOUT], X2[wtp::MOUT], ACC[wtp::MOUT];
    unsigned long long p = 0ULL;
    #pragma unroll
    for (int m = 0; m < wtp::MOUT; m++) {
        X1[m]  = x1p[m * (wtp::C / 2)];
        X2[m]  = x2p[m * (wtp::C / 2)];
        ACC[m] = 0ULL;
    }

    run_terms(std::make_integer_sequence<int, wtp::NNZ>{}, cgw_s + cp, X1, X2, ACC, p);

    #pragma unroll
    for (int m = 0; m < wtp::MOUT; m++)
        op[m * (wtp::C / 2)] = ACC[m];
}

// ============================================================================
// Launch. Inputs (metadata order): x1, x2, weight, CG_vals, M1, M2, l_ind, M_seg
// ============================================================================
extern "C" void kernel_launch(void* const* d_in, const int* in_sizes, int n_in,
                              void* d_out, int out_size)
{
    const float* x1    = (const float*)d_in[0];
    const float* x2    = (const float*)d_in[1];
    const float* w     = (const float*)d_in[2];
    const float* cg    = (const float*)d_in[3];
    const int*   l_ind = (const int*)d_in[6];
    float*       out   = (float*)d_out;

    const int B = in_sizes[0] / (wtp::MOUT * wtp::C);   // 2048
    const int smem = wtp::NNZ * wtp::NCHP * 8;          // 61184 bytes

    cudaFuncSetAttribute(wtp_kernel, cudaFuncAttributeMaxDynamicSharedMemorySize, smem);

    const int grid = (B / wtp::NROW) * 4;               // row-groups x 4 channel-groups
    wtp_kernel<<<grid, wtp::NTHREADS, smem>>>(x1, x2, w, cg, l_ind, out);
}

// round 2
// speedup vs baseline: 1.1509x; 1.1509x over previous
#include <cuda_runtime.h>
#include <cstdint>
#include <utility>

// ============================================================================
// Compile-time structure builder. Reproduces the reference enumeration exactly
// (to get each term's original index into CG_vals), then re-sorts terms:
//   major: m_total = m1+m2  (7 groups, -3..3)
//   mid:   (M1, M2) pair    (pair products factorized; a pair lives in one group)
//   minor: l (output degree) -> accumulator slot l - |m|
// Within a group only (4-|m|) output segments are live -> tiny ACC window.
// ============================================================================
namespace wtp {

constexpr int LMAX = 3;
constexpr int MOUT = 16;
constexpr int NNZ  = 478;
constexpr int C    = 128;
constexpr int NCHP = 8;        // channel-pairs per block (16 channels)
constexpr int NROW = 16;       // row slots per block
constexpr int NTHREADS = NCHP * NROW;  // 128
constexpr int NGRP = 7;        // m_total in -3..3

struct Structure {
    int m1[NNZ];
    int m2[NNZ];
    int aidx[NNZ];     // accumulator slot = l - |m|
    int orig[NNZ];     // original reference-order index (CG table slot)
    bool newpair[NNZ];
    int start[NGRP + 1];
    int count;
};

constexpr Structure build_structure() {
    Structure s{};
    // --- triples (l, l1, l2) in reference order ---
    int tl[64] = {}, tl1[64] = {}, tl2[64] = {};
    int nt = 0;
    for (int l1 = 0; l1 <= LMAX; l1++)
        for (int l2 = 0; l2 <= LMAX; l2++) {
            int lo = (l1 > l2) ? (l1 - l2) : (l2 - l1);
            int hi = (l1 + l2 < LMAX) ? (l1 + l2) : LMAX;
            for (int l = lo; l <= hi; l++) { tl[nt]=l; tl1[nt]=l1; tl2[nt]=l2; nt++; }
        }
    // --- terms in reference order ---
    int rm1[NNZ]={}, rm2[NNZ]={}, rl[NNZ]={}, rm[NNZ]={};
    int cnt = 0;
    for (int l = 0; l <= LMAX; l++)
        for (int m = -l; m <= l; m++) {
            for (int t = 0; t < nt; t++) {
                if (tl[t] != l) continue;
                int l1 = tl1[t], l2 = tl2[t];
                int lo = (-l1 > m - l2) ? -l1 : (m - l2);
                int hi = (l1 < m + l2) ? l1 : (m + l2);
                for (int m1 = lo; m1 <= hi; m1++) {
                    int m2 = m - m1;
                    rm1[cnt] = l1*l1 + l1 + m1;
                    rm2[cnt] = l2*l2 + l2 + m2;
                    rl[cnt]  = l;
                    rm[cnt]  = m;
                    cnt++;
                }
            }
        }
    s.count = cnt;
    // --- stable sort by (m_total, M1, M2, l) via rank counting ---
    int key[NNZ] = {};
    for (int i = 0; i < cnt; i++)
        key[i] = (((rm[i] + 3) * 16 + rm1[i]) * 16 + rm2[i]) * 4 + rl[i];
    int sm[NNZ] = {};   // sorted m_total per slot (for group starts)
    for (int i = 0; i < cnt; i++) {
        int rank = 0;
        for (int j = 0; j < cnt; j++)
            if (key[j] < key[i] || (key[j] == key[i] && j < i)) rank++;
        int am = rm[i] < 0 ? -rm[i] : rm[i];
        s.m1[rank]   = rm1[i];
        s.m2[rank]   = rm2[i];
        s.aidx[rank] = rl[i] - am;
        s.orig[rank] = i;
        sm[rank]     = rm[i];
    }
    for (int i = 0; i < cnt; i++)
        s.newpair[i] = (i == 0) || (s.m1[i] != s.m1[i-1]) || (s.m2[i] != s.m2[i-1]);
    // group start offsets: start[g] = first index with m_total >= g-3
    for (int g = 0; g <= NGRP; g++) {
        int st = cnt;
        for (int i = 0; i < cnt; i++)
            if (sm[i] + 3 >= g) { st = i; break; }
        s.start[g] = st;
    }
    return s;
}

constexpr Structure S = build_structure();
static_assert(S.count == NNZ, "term count mismatch vs reference structure");
static_assert(S.start[0] == 0 && S.start[NGRP] == NNZ, "group partition broken");

} // namespace wtp

// ============================================================================
// Per-term executor: all indices compile-time. Packed f32x2 math (2 ch/thread).
// ============================================================================
template <int T>
__device__ __forceinline__ void do_term(
    const unsigned long long* __restrict__ cgw_tp,
    const unsigned long long (&X1)[wtp::MOUT],
    const unsigned long long (&X2)[wtp::MOUT],
    unsigned long long (&ACC)[4],
    unsigned long long& p)
{
    constexpr int m1 = wtp::S.m1[T];
    constexpr int m2 = wtp::S.m2[T];
    constexpr int ai = wtp::S.aidx[T];
    constexpr int og = wtp::S.orig[T];
    if constexpr (wtp::S.newpair[T]) {
        asm("mul.rn.f32x2 %0, %1, %2;" : "=l"(p) : "l"(X1[m1]), "l"(X2[m2]));
    }
    const unsigned long long wv = cgw_tp[og * wtp::NCHP];
    asm("fma.rn.f32x2 %0, %1, %2, %3;" : "=l"(ACC[ai]) : "l"(p), "l"(wv), "l"(ACC[ai]));
}

template <int Base, int... Is>
__device__ __forceinline__ void run_range(
    std::integer_sequence<int, Is...>,
    const unsigned long long* __restrict__ cgw_tp,
    const unsigned long long (&X1)[wtp::MOUT],
    const unsigned long long (&X2)[wtp::MOUT],
    unsigned long long (&ACC)[4],
    unsigned long long& p)
{
    ((do_term<Base + Is>(cgw_tp, X1, X2, ACC, p)), ...);
}

// One m_total group: zero its ACC window, run its terms, store its segments.
template <int G>
__device__ __forceinline__ void run_group(
    const unsigned long long* __restrict__ cgw_tp,
    const unsigned long long (&X1)[wtp::MOUT],
    const unsigned long long (&X2)[wtp::MOUT],
    unsigned long long* __restrict__ op)
{
    constexpr int m  = G - 3;
    constexpr int la = m < 0 ? -m : m;
    constexpr int ns = 4 - la;                  // live output segments
    constexpr int nb = wtp::S.start[G];
    constexpr int ne = wtp::S.start[G + 1];

    unsigned long long ACC[4] = {0ULL, 0ULL, 0ULL, 0ULL};
    unsigned long long p = 0ULL;
    run_range<nb>(std::make_integer_sequence<int, ne - nb>{}, cgw_tp, X1, X2, ACC, p);

    #pragma unroll
    for (int i = 0; i < ns; i++) {
        constexpr int CC = wtp::C / 2;
        const int l = la + i;
        op[(l * l + l + m) * CC] = ACC[i];
    }
}

// ============================================================================
// Kernel. Block = 128 threads = 8 ch-pairs x 16 row-slots (16 channels,
// 16 rows). Shared cgw[478][8] f32x2 = 30592 B. Target 5 blocks/SM.
// ============================================================================
__global__ void __launch_bounds__(wtp::NTHREADS, 5)
wtp_kernel(const float* __restrict__ x1,
           const float* __restrict__ x2,
           const float* __restrict__ w,
           const float* __restrict__ cg,
           const int*   __restrict__ l_ind,
           float* __restrict__ out)
{
    extern __shared__ unsigned long long cgw_s[];  // [NNZ * NCHP] packed f32x2

    const int tid     = threadIdx.x;
    const int cgroup  = blockIdx.x & 7;                 // 8 groups of 16 channels
    const int rowbase = (blockIdx.x >> 3) * wtp::NROW;
    const int cp      = tid & (wtp::NCHP - 1);
    const int rs      = tid >> 3;
    const int cbase   = cgroup * 16;

    // --- per-block CG*weight table (runtime CG / l_ind / weight) ---
    {
        float2* cgw_f = reinterpret_cast<float2*>(cgw_s);
        #pragma unroll 4
        for (int i = tid; i < wtp::NNZ * wtp::NCHP; i += wtp::NTHREADS) {
            const int t  = i >> 3;       // term, reference order
            const int pc = i & 7;        // channel-pair
            const float cgv = __ldg(cg + t);
            const int   li  = __ldg(l_ind + t);
            const float2 wv =
                *reinterpret_cast<const float2*>(w + li * wtp::C + cbase + pc * 2);
            cgw_f[i] = make_float2(cgv * wv.x, cgv * wv.y);
        }
    }
    __syncthreads();

    const int row = rowbase + rs;
    const size_t base = (size_t)row * wtp::MOUT * wtp::C + cbase + cp * 2;
    const unsigned long long* x1p = reinterpret_cast<const unsigned long long*>(x1 + base);
    const unsigned long long* x2p = reinterpret_cast<const unsigned long long*>(x2 + base);
    unsigned long long*       op  = reinterpret_cast<unsigned long long*>(out + base);

    unsigned long long X1[wtp::MOUT], X2[wtp::MOUT];
    #pragma unroll
    for (int m = 0; m < wtp::MOUT; m++) {
        X1[m] = x1p[m * (wtp::C / 2)];
        X2[m] = x2p[m * (wtp::C / 2)];
    }

    const unsigned long long* cgw_tp = cgw_s + cp;
    run_group<0>(cgw_tp, X1, X2, op);
    run_group<1>(cgw_tp, X1, X2, op);
    run_group<2>(cgw_tp, X1, X2, op);
    run_group<3>(cgw_tp, X1, X2, op);
    run_group<4>(cgw_tp, X1, X2, op);
    run_group<5>(cgw_tp, X1, X2, op);
    run_group<6>(cgw_tp, X1, X2, op);
}

// ============================================================================
// Launch. Inputs (metadata order): x1, x2, weight, CG_vals, M1, M2, l_ind, M_seg
// ============================================================================
extern "C" void kernel_launch(void* const* d_in, const int* in_sizes, int n_in,
                              void* d_out, int out_size)
{
    const float* x1    = (const float*)d_in[0];
    const float* x2    = (const float*)d_in[1];
    const float* w     = (const float*)d_in[2];
    const float* cg    = (const float*)d_in[3];
    const int*   l_ind = (const int*)d_in[6];
    float*       out   = (float*)d_out;

    const int B = in_sizes[0] / (wtp::MOUT * wtp::C);   // 2048
    const int smem = wtp::NNZ * wtp::NCHP * 8;          // 30592 bytes

    cudaFuncSetAttribute(wtp_kernel, cudaFuncAttributeMaxDynamicSharedMemorySize, smem);

    const int grid = (B / wtp::NROW) * (wtp::C / 16);   // 128 * 8 = 1024
    wtp_kernel<<<grid, wtp::NTHREADS, smem>>>(x1, x2, w, cg, l_ind, out);
}

// round 3
// speedup vs baseline: 1.3535x; 1.1761x over previous
#include <cuda_runtime.h>
#include <cstdint>
#include <utility>

// ============================================================================
// Compile-time structure builder. Reproduces the reference enumeration exactly
// (to recover each term's original index into CG_vals), then re-sorts terms:
//   major: m_total = m1+m2  (7 groups, -3..3)
//   mid:   (M1, M2) pair    (pair products factorized)
//   minor: l (output degree) -> accumulator slot l - |m|
// ============================================================================
namespace wtp {

constexpr int LMAX = 3;
constexpr int MOUT = 16;
constexpr int NNZ  = 478;
constexpr int C    = 128;
constexpr int NCHP = 8;        // channel-pairs per block (16 channels)
constexpr int NSLOT = 16;      // row slots per block
constexpr int RPT  = 2;        // rows per thread (wv register reuse)
constexpr int NROWB = NSLOT * RPT;  // 32 rows per block
constexpr int NTHREADS = NCHP * NSLOT;  // 128
constexpr int NGRP = 7;

struct Structure {
    int m1[NNZ];
    int m2[NNZ];
    int aidx[NNZ];
    int orig[NNZ];
    bool newpair[NNZ];
    int start[NGRP + 1];
    int count;
};

constexpr Structure build_structure() {
    Structure s{};
    int tl[64] = {}, tl1[64] = {}, tl2[64] = {};
    int nt = 0;
    for (int l1 = 0; l1 <= LMAX; l1++)
        for (int l2 = 0; l2 <= LMAX; l2++) {
            int lo = (l1 > l2) ? (l1 - l2) : (l2 - l1);
            int hi = (l1 + l2 < LMAX) ? (l1 + l2) : LMAX;
            for (int l = lo; l <= hi; l++) { tl[nt]=l; tl1[nt]=l1; tl2[nt]=l2; nt++; }
        }
    int rm1[NNZ]={}, rm2[NNZ]={}, rl[NNZ]={}, rm[NNZ]={};
    int cnt = 0;
    for (int l = 0; l <= LMAX; l++)
        for (int m = -l; m <= l; m++) {
            for (int t = 0; t < nt; t++) {
                if (tl[t] != l) continue;
                int l1 = tl1[t], l2 = tl2[t];
                int lo = (-l1 > m - l2) ? -l1 : (m - l2);
                int hi = (l1 < m + l2) ? l1 : (m + l2);
                for (int m1 = lo; m1 <= hi; m1++) {
                    int m2 = m - m1;
                    rm1[cnt] = l1*l1 + l1 + m1;
                    rm2[cnt] = l2*l2 + l2 + m2;
                    rl[cnt]  = l;
                    rm[cnt]  = m;
                    cnt++;
                }
            }
        }
    s.count = cnt;
    int key[NNZ] = {};
    for (int i = 0; i < cnt; i++)
        key[i] = (((rm[i] + 3) * 16 + rm1[i]) * 16 + rm2[i]) * 4 + rl[i];
    int sm[NNZ] = {};
    for (int i = 0; i < cnt; i++) {
        int rank = 0;
        for (int j = 0; j < cnt; j++)
            if (key[j] < key[i] || (key[j] == key[i] && j < i)) rank++;
        int am = rm[i] < 0 ? -rm[i] : rm[i];
        s.m1[rank]   = rm1[i];
        s.m2[rank]   = rm2[i];
        s.aidx[rank] = rl[i] - am;
        s.orig[rank] = i;
        sm[rank]     = rm[i];
    }
    for (int i = 0; i < cnt; i++)
        s.newpair[i] = (i == 0) || (s.m1[i] != s.m1[i-1]) || (s.m2[i] != s.m2[i-1]);
    for (int g = 0; g <= NGRP; g++) {
        int st = cnt;
        for (int i = 0; i < cnt; i++)
            if (sm[i] + 3 >= g) { st = i; break; }
        s.start[g] = st;
    }
    return s;
}

constexpr Structure S = build_structure();
static_assert(S.count == NNZ, "term count mismatch vs reference structure");
static_assert(S.start[0] == 0 && S.start[NGRP] == NNZ, "group partition broken");

} // namespace wtp

using ull = unsigned long long;

// ============================================================================
// Per-term executor: compile-time indices, packed f32x2 math, ONE shared-mem
// wv load serving RPT=2 rows (the key: halves crossbar bytes per output).
// ============================================================================
template <int T>
__device__ __forceinline__ void do_term(
    const ull* __restrict__ cgw_tp,
    const ull (&X1)[wtp::RPT][wtp::MOUT],
    const ull (&X2)[wtp::RPT][wtp::MOUT],
    ull (&ACC)[wtp::RPT][4],
    ull (&p)[wtp::RPT])
{
    constexpr int m1 = wtp::S.m1[T];
    constexpr int m2 = wtp::S.m2[T];
    constexpr int ai = wtp::S.aidx[T];
    constexpr int og = wtp::S.orig[T];
    if constexpr (wtp::S.newpair[T]) {
        asm("mul.rn.f32x2 %0, %1, %2;" : "=l"(p[0]) : "l"(X1[0][m1]), "l"(X2[0][m2]));
        asm("mul.rn.f32x2 %0, %1, %2;" : "=l"(p[1]) : "l"(X1[1][m1]), "l"(X2[1][m2]));
    }
    const ull wv = cgw_tp[og * wtp::NCHP];
    asm("fma.rn.f32x2 %0, %1, %2, %3;" : "=l"(ACC[0][ai]) : "l"(p[0]), "l"(wv), "l"(ACC[0][ai]));
    asm("fma.rn.f32x2 %0, %1, %2, %3;" : "=l"(ACC[1][ai]) : "l"(p[1]), "l"(wv), "l"(ACC[1][ai]));
}

template <int Base, int... Is>
__device__ __forceinline__ void run_range(
    std::integer_sequence<int, Is...>,
    const ull* __restrict__ cgw_tp,
    const ull (&X1)[wtp::RPT][wtp::MOUT],
    const ull (&X2)[wtp::RPT][wtp::MOUT],
    ull (&ACC)[wtp::RPT][4],
    ull (&p)[wtp::RPT])
{
    ((do_term<Base + Is>(cgw_tp, X1, X2, ACC, p)), ...);
}

template <int G>
__device__ __forceinline__ void run_group(
    const ull* __restrict__ cgw_tp,
    const ull (&X1)[wtp::RPT][wtp::MOUT],
    const ull (&X2)[wtp::RPT][wtp::MOUT],
    ull* __restrict__ op0,
    ull* __restrict__ op1)
{
    constexpr int m  = G - 3;
    constexpr int la = m < 0 ? -m : m;
    constexpr int ns = 4 - la;
    constexpr int nb = wtp::S.start[G];
    constexpr int ne = wtp::S.start[G + 1];

    ull ACC[wtp::RPT][4] = {};
    ull p[wtp::RPT] = {};
    run_range<nb>(std::make_integer_sequence<int, ne - nb>{}, cgw_tp, X1, X2, ACC, p);

    #pragma unroll
    for (int i = 0; i < ns; i++) {
        constexpr int CC = wtp::C / 2;
        const int l = la + i;
        op0[(l * l + l + m) * CC] = ACC[0][i];
        op1[(l * l + l + m) * CC] = ACC[1][i];
    }
}

// ============================================================================
// Kernel. Block = 128 threads = 8 ch-pairs x 16 row-slots; each thread owns
// 2 rows (rs and rs+16) -> block covers 16 channels x 32 rows.
// Shared cgw[478][8] f32x2 = 30592 B. 3 blocks/SM (reg-bound).
// ============================================================================
__global__ void __launch_bounds__(wtp::NTHREADS, 3)
wtp_kernel(const float* __restrict__ x1,
           const float* __restrict__ x2,
           const float* __restrict__ w,
           const float* __restrict__ cg,
           const int*   __restrict__ l_ind,
           float* __restrict__ out)
{
    extern __shared__ ull cgw_s[];  // [NNZ * NCHP] packed f32x2

    const int tid     = threadIdx.x;
    const int cgroup  = blockIdx.x & 7;                  // 8 groups of 16 channels
    const int rowbase = (blockIdx.x >> 3) * wtp::NROWB;  // 32 rows per block
    const int cp      = tid & (wtp::NCHP - 1);
    const int rs      = tid >> 3;                        // 0..15
    const int cbase   = cgroup * 16;

    // --- per-block CG*weight table (runtime CG / l_ind / weight) ---
    {
        float2* cgw_f = reinterpret_cast<float2*>(cgw_s);
        #pragma unroll 4
        for (int i = tid; i < wtp::NNZ * wtp::NCHP; i += wtp::NTHREADS) {
            const int t  = i >> 3;
            const int pc = i & 7;
            const float cgv = __ldg(cg + t);
            const int   li  = __ldg(l_ind + t);
            const float2 wv =
                *reinterpret_cast<const float2*>(w + li * wtp::C + cbase + pc * 2);
            cgw_f[i] = make_float2(cgv * wv.x, cgv * wv.y);
        }
    }
    __syncthreads();

    const int row0 = rowbase + rs;
    const int row1 = row0 + wtp::NSLOT;
    const size_t base0 = (size_t)row0 * wtp::MOUT * wtp::C + cbase + cp * 2;
    const size_t base1 = (size_t)row1 * wtp::MOUT * wtp::C + cbase + cp * 2;
    const ull* x1p0 = reinterpret_cast<const ull*>(x1 + base0);
    const ull* x2p0 = reinterpret_cast<const ull*>(x2 + base0);
    const ull* x1p1 = reinterpret_cast<const ull*>(x1 + base1);
    const ull* x2p1 = reinterpret_cast<const ull*>(x2 + base1);
    ull* op0 = reinterpret_cast<ull*>(out + base0);
    ull* op1 = reinterpret_cast<ull*>(out + base1);

    ull X1[wtp::RPT][wtp::MOUT], X2[wtp::RPT][wtp::MOUT];
    #pragma unroll
    for (int m = 0; m < wtp::MOUT; m++) {
        constexpr int CC = wtp::C / 2;
        X1[0][m] = x1p0[m * CC];
        X2[0][m] = x2p0[m * CC];
        X1[1][m] = x1p1[m * CC];
        X2[1][m] = x2p1[m * CC];
    }

    const ull* cgw_tp = cgw_s + cp;
    run_group<0>(cgw_tp, X1, X2, op0, op1);
    run_group<1>(cgw_tp, X1, X2, op0, op1);
    run_group<2>(cgw_tp, X1, X2, op0, op1);
    run_group<3>(cgw_tp, X1, X2, op0, op1);
    run_group<4>(cgw_tp, X1, X2, op0, op1);
    run_group<5>(cgw_tp, X1, X2, op0, op1);
    run_group<6>(cgw_tp, X1, X2, op0, op1);
}

// ============================================================================
// Launch. Inputs (metadata order): x1, x2, weight, CG_vals, M1, M2, l_ind, M_seg
// ============================================================================
extern "C" void kernel_launch(void* const* d_in, const int* in_sizes, int n_in,
                              void* d_out, int out_size)
{
    const float* x1    = (const float*)d_in[0];
    const float* x2    = (const float*)d_in[1];
    const float* w     = (const float*)d_in[2];
    const float* cg    = (const float*)d_in[3];
    const int*   l_ind = (const int*)d_in[6];
    float*       out   = (float*)d_out;

    const int B = in_sizes[0] / (wtp::MOUT * wtp::C);   // 2048
    const int smem = wtp::NNZ * wtp::NCHP * 8;          // 30592 bytes

    cudaFuncSetAttribute(wtp_kernel, cudaFuncAttributeMaxDynamicSharedMemorySize, smem);

    const int grid = (B / wtp::NROWB) * (wtp::C / 16);  // 64 * 8 = 512
    wtp_kernel<<<grid, wtp::NTHREADS, smem>>>(x1, x2, w, cg, l_ind, out);
}